// round 13
// baseline (speedup 1.0000x reference)
#include <cuda_runtime.h>
#include <cuda_fp16.h>
#include <cstdint>

// Problem dims (fixed by the reference)
#define BSZ   2
#define LEN   1024
#define DM    1024
#define DI    2048
#define DS    16
#define DR    64
#define MROWS (BSZ*LEN)     // 2048
#define NSEG  16
#define TSEG  (LEN/NSEG)    // 64

// ---------------------------------------------------------------------------
// Scratch (allocation-free: __device__ globals)
// ---------------------------------------------------------------------------
__device__ float  g_xz   [MROWS * 2 * DI];  // in_proj out (x | z), fp32
__device__ float  g_x    [MROWS * DI];      // conv+silu out fp32 (scan)
__device__ __half g_xh   [MROWS * DI];      // conv+silu out half (x_proj A)
__device__ float  g_xdbl [MROWS * 96];      // x_proj out (dt_r | B | C) fp32
__device__ __half g_dtrh [MROWS * DR];      // x_dbl[:, :64] half (dt_proj A)
__device__ float  g_dt   [MROWS * DI];      // softplus dt fp32
__device__ __half g_yh   [MROWS * DI];      // gated scan out half (out_proj A)
__device__ float  g_P    [BSZ * DI * NSEG * DS];
__device__ float  g_Q    [BSZ * DI * NSEG * DS];
__device__ float  g_hin  [BSZ * DI * NSEG * DS];

__device__ __half g_hidh [MROWS * DM];      // hidden in half
__device__ __half g_inwh [2 * DI * DM];     // in_proj_w half
__device__ __half g_xpwh [96 * DI];         // x_proj_w half
__device__ __half g_dtwh [DI * DR];         // dt_proj_w half
__device__ __half g_otwh [DM * DI];         // out_proj_w half

__device__ __forceinline__ void cpa16(void* dst, const void* src, int sz) {
    uint32_t d = (uint32_t)__cvta_generic_to_shared(dst);
    asm volatile("cp.async.cg.shared.global [%0], [%1], 16, %2;\n"
                 :: "r"(d), "l"(src), "r"(sz) : "memory");
}

__device__ __forceinline__ void ldmx4(uint32_t& r0, uint32_t& r1,
                                      uint32_t& r2, uint32_t& r3,
                                      const void* p) {
    uint32_t a = (uint32_t)__cvta_generic_to_shared(p);
    asm volatile("ldmatrix.sync.aligned.m8n8.x4.shared.b16 {%0,%1,%2,%3}, [%4];"
                 : "=r"(r0), "=r"(r1), "=r"(r2), "=r"(r3) : "r"(a));
}

// ---------------------------------------------------------------------------
// fp16 GEMM v10: C[M,N] (+)= A[M,Kslice] * W[N,Kslice]^T, fp32 acc.
// CTA tile 128x128, 256 threads = 8 warps (2m x 4n), warp tile 64x32.
// K stage BK=64 halfs, NS=2 double buffer: per sync-phase each warp does
// 24 ldmatrix.x4 + 64 HMMA (halved sync cadence vs BK=32).
// smem 72KB/CTA (144B rows, conflict-free), 2 CTAs/SM (regs<=128).
// grid.z splits K; atomic=1 -> atomicAdd; act==1 -> softplus(+bias).
// M%128==0, ksplit%64==0 or ksplit==64 required (true at call sites).
// ---------------------------------------------------------------------------
#define BK 64
#define NS 2
#define SSTR 72                    // halfs per smem row (144B, conflict-free)
#define ABUF (128 * SSTR)          // halfs per stage per matrix
#define SMEM_BYTES (2 * NS * ABUF * 2)   // 73728

__global__ void __launch_bounds__(256, 2) gemm_h(
    const __half* __restrict__ A, int lda,
    const __half* __restrict__ W, int ldw,
    float* __restrict__ C, int ldc,
    int N, int ksplit,
    const float* __restrict__ bias, int act, int atomic)
{
    extern __shared__ __half sm[];
    __half* Asm = sm;
    __half* Wsm = sm + NS * ABUF;

    const int bm   = blockIdx.y * 128;
    const int bn   = blockIdx.x * 128;
    const int kb   = blockIdx.z * ksplit;
    const int tid  = threadIdx.x;
    const int warp = tid >> 5;
    const int lane = tid & 31;
    const int wm   = (warp & 1) * 64;
    const int wn   = (warp >> 1) * 32;
    const int g    = lane >> 2;
    const int tg   = lane & 3;

    // loader: row lr (0..127), 4 consecutive 16B chunks starting at half lc
    const int lr = tid >> 1;               // 0..127
    const int lc = (tid & 1) * 32;         // 0 or 32 halfs
    const bool wrow_ok = (bn + lr < N);
    const __half* ap = &A[(bm + lr) * lda + kb + lc];
    const __half* wp = &W[(bn + lr) * ldw + kb + lc];
    __half* asd = &Asm[lr * SSTR + lc];
    __half* wsd = &Wsm[lr * SSTR + lc];

    const int arow = wm + (lane & 15);
    const int akof = (lane >> 4) * 8;
    const int brow = wn + (lane & 7) + ((lane >> 4) << 3);
    const int bkof = ((lane >> 3) & 1) * 8;

    float acc[4][4][4];
#pragma unroll
    for (int i = 0; i < 4; i++)
#pragma unroll
        for (int j = 0; j < 4; j++)
#pragma unroll
            for (int c = 0; c < 4; c++) acc[i][j][c] = 0.f;

    const int nstage = (ksplit + BK - 1) / BK;     // K=64 -> 1 stage
    const int ktail  = ksplit - (nstage - 1) * BK; // halfs in last stage

    // prologue: stage 0
    {
        const int vz  = (ktail >= BK || nstage > 1) ? 16 : 16; // stage0 full or K=64 exact
        const int vzw = wrow_ok ? 16 : 0;
#pragma unroll
        for (int q = 0; q < 4; q++) {
            cpa16(asd + 8 * q, ap + 8 * q, (lc + 8 * q < ksplit) ? vz : 0);
            cpa16(wsd + 8 * q, wp + 8 * q, (lc + 8 * q < ksplit) ? vzw : 0);
        }
        asm volatile("cp.async.commit_group;" ::: "memory");
    }

    for (int s = 0; s < nstage; s++) {
        const int buf = s & 1;
        asm volatile("cp.async.wait_group 0;" ::: "memory");
        __syncthreads();

        // prefetch stage s+1 into other buffer
        if (s + 1 < nstage) {
            const int pb = (s + 1) & 1;
            const int ks = (s + 1) * BK;
            const int vzw = wrow_ok ? 16 : 0;
#pragma unroll
            for (int q = 0; q < 4; q++) {
                int ok = (ks + lc + 8 * q < ksplit) ? 1 : 0;
                cpa16(asd + (size_t)pb * ABUF + 8 * q, ap + ks + 8 * q, ok ? 16 : 0);
                cpa16(wsd + (size_t)pb * ABUF + 8 * q, wp + ks + 8 * q, ok ? vzw : 0);
            }
            asm volatile("cp.async.commit_group;" ::: "memory");
        }

        const __half* ab = Asm + (size_t)buf * ABUF;
        const __half* wb = Wsm + (size_t)buf * ABUF;
        const int klim = (s + 1 < nstage) ? BK : ktail;
#pragma unroll
        for (int kk = 0; kk < BK; kk += 16) {
            if (kk >= klim) break;
            uint32_t a[4][4], b[8];
#pragma unroll
            for (int mi = 0; mi < 4; mi++)
                ldmx4(a[mi][0], a[mi][1], a[mi][2], a[mi][3],
                      ab + (arow + 16 * mi) * SSTR + kk + akof);
            ldmx4(b[0], b[1], b[2], b[3],
                  wb + brow * SSTR + kk + bkof);
            ldmx4(b[4], b[5], b[6], b[7],
                  wb + (brow + 16) * SSTR + kk + bkof);
#pragma unroll
            for (int mi = 0; mi < 4; mi++)
#pragma unroll
                for (int jf = 0; jf < 4; jf++)
                    asm volatile(
                        "mma.sync.aligned.m16n8k16.row.col.f32.f16.f16.f32 "
                        "{%0,%1,%2,%3},{%4,%5,%6,%7},{%8,%9},{%0,%1,%2,%3};"
                        : "+f"(acc[mi][jf][0]), "+f"(acc[mi][jf][1]),
                          "+f"(acc[mi][jf][2]), "+f"(acc[mi][jf][3])
                        : "r"(a[mi][0]), "r"(a[mi][1]),
                          "r"(a[mi][2]), "r"(a[mi][3]),
                          "r"(b[2 * jf]), "r"(b[2 * jf + 1]));
        }
        if (s + 1 < nstage) __syncthreads();
    }

#pragma unroll
    for (int mi = 0; mi < 4; mi++)
#pragma unroll
        for (int jf = 0; jf < 4; jf++) {
            const int nn = bn + wn + jf * 8 + tg * 2;
            if (nn < N) {
                const int m0 = bm + wm + mi * 16 + g;
                float v0 = acc[mi][jf][0], v1 = acc[mi][jf][1];
                float v2 = acc[mi][jf][2], v3 = acc[mi][jf][3];
                if (act) {
                    const float b0 = bias[nn], b1 = bias[nn + 1];
                    v0 += b0; v1 += b1; v2 += b0; v3 += b1;
                    v0 = (v0 > 20.f) ? v0 : log1pf(__expf(v0));
                    v1 = (v1 > 20.f) ? v1 : log1pf(__expf(v1));
                    v2 = (v2 > 20.f) ? v2 : log1pf(__expf(v2));
                    v3 = (v3 > 20.f) ? v3 : log1pf(__expf(v3));
                }
                if (atomic) {
                    atomicAdd(&C[m0 * ldc + nn],           v0);
                    atomicAdd(&C[m0 * ldc + nn + 1],       v1);
                    atomicAdd(&C[(m0 + 8) * ldc + nn],     v2);
                    atomicAdd(&C[(m0 + 8) * ldc + nn + 1], v3);
                } else {
                    *(float2*)&C[m0 * ldc + nn]       = make_float2(v0, v1);
                    *(float2*)&C[(m0 + 8) * ldc + nn] = make_float2(v2, v3);
                }
            }
        }
}

// ---------------------------------------------------------------------------
// fp32 -> fp16 conversions
// ---------------------------------------------------------------------------
#define CS0 (MROWS * DM)
#define CS1 (2 * DI * DM)
#define CS2 (96 * DI)
#define CS3 (DI * DR)
#define CS4 (DM * DI)
#define CWT ((CS1 + CS2 + CS3 + CS4) / 4)

__global__ void convert_w(const float* __restrict__ inw,
                          const float* __restrict__ xpw,
                          const float* __restrict__ dtw,
                          const float* __restrict__ otw)
{
    int t = blockIdx.x * 512 + threadIdx.x;
    if (t >= CWT) return;
    int i = t * 4;
    const float* src; __half* dst; int off;
    if (i < CS1) {
        src = inw; dst = g_inwh; off = i;
    } else if ((i -= CS1) < CS2) {
        src = xpw; dst = g_xpwh; off = i;
    } else if ((i -= CS2) < CS3) {
        src = dtw; dst = g_dtwh; off = i;
    } else {
        src = otw; dst = g_otwh; off = i - CS3;
    }
    float4 v = *(const float4*)(src + off);
    *(__half2*)(dst + off)     = __floats2half2_rn(v.x, v.y);
    *(__half2*)(dst + off + 2) = __floats2half2_rn(v.z, v.w);
}

__global__ void convert_hid(const float* __restrict__ hid)
{
    int t = blockIdx.x * 512 + threadIdx.x;
    if (t >= CS0 / 4) return;
    int off = t * 4;
    float4 v = *(const float4*)(hid + off);
    *(__half2*)(g_hidh + off)     = __floats2half2_rn(v.x, v.y);
    *(__half2*)(g_hidh + off + 2) = __floats2half2_rn(v.z, v.w);
}

__global__ void dtr2h_kernel(const float* __restrict__ xdbl, __half* __restrict__ d)
{
    int i = blockIdx.x * 512 + threadIdx.x;
    if (i < MROWS * DR) {
        int r = i >> 6, c = i & 63;
        d[i] = __float2half_rn(xdbl[r * 96 + c]);
    }
}

__global__ void zero_kernel(float* __restrict__ p, int n)
{
    int i = blockIdx.x * 512 + threadIdx.x;
    if (i < n) p[i] = 0.f;
}

// ---------------------------------------------------------------------------
// Depthwise causal conv (K=4) + bias + SiLU.
// ---------------------------------------------------------------------------
__global__ void conv_silu_kernel(const float* __restrict__ xz,
                                 const float* __restrict__ w,
                                 const float* __restrict__ bias,
                                 float* __restrict__ xout,
                                 __half* __restrict__ xhout)
{
    int idx = blockIdx.x * blockDim.x + threadIdx.x;
    int d  = idx & (DI - 1);
    int bl = idx >> 11;
    int l  = bl & (LEN - 1);
    float accv = bias[d];
#pragma unroll
    for (int k = 0; k < 4; k++) {
        int ll = l + k - 3;
        if (ll >= 0)
            accv += xz[(bl + (ll - l)) * (2 * DI) + d] * w[d * 4 + k];
    }
    float v = accv / (1.f + __expf(-accv));
    xout[idx]  = v;
    xhout[idx] = __float2half_rn(v);
}

// ---------------------------------------------------------------------------
// Segmented selective scan, state-per-thread (16 states in registers).
// ---------------------------------------------------------------------------
__global__ void __launch_bounds__(256) scanA(
    const float* __restrict__ dtp,
    const float* __restrict__ xp,
    const float* __restrict__ xdbl,
    const float* __restrict__ A_log,
    float* __restrict__ P, float* __restrict__ Q)
{
    __shared__ float sB[TSEG][DS];

    const int d   = blockIdx.x * 256 + threadIdx.x;
    const int seg = blockIdx.y;
    const int b   = blockIdx.z;
    const int t0  = seg * TSEG;

    for (int e = threadIdx.x; e < TSEG * DS; e += 256) {
        int t = e >> 4, n = e & 15;
        sB[t][n] = xdbl[(b * LEN + t0 + t) * 96 + 64 + n];
    }
    __syncthreads();

    float a[DS], h[DS];
#pragma unroll
    for (int n = 0; n < DS; n++) {
        a[n] = -__expf(A_log[d * DS + n]);
        h[n] = 0.f;
    }

    const int gi = (b * LEN + t0) * DI + d;
    float Sdt = 0.f;
    float dt_c = dtp[gi], x_c = xp[gi];

    for (int t = 0; t < TSEG; t++) {
        float dt_n = 0.f, x_n = 0.f;
        if (t + 1 < TSEG) {
            dt_n = dtp[gi + (t + 1) * DI];
            x_n  = xp[gi + (t + 1) * DI];
        }
        const float dtx = dt_c * x_c;
        Sdt += dt_c;
        float bb[DS];
        *(float4*)&bb[0]  = *(const float4*)&sB[t][0];
        *(float4*)&bb[4]  = *(const float4*)&sB[t][4];
        *(float4*)&bb[8]  = *(const float4*)&sB[t][8];
        *(float4*)&bb[12] = *(const float4*)&sB[t][12];
#pragma unroll
        for (int n = 0; n < DS; n++) {
            float dA = __expf(dt_c * a[n]);
            h[n] = fmaf(dA, h[n], bb[n] * dtx);
        }
        dt_c = dt_n; x_c = x_n;
    }

    const int pb = ((b * DI + d) * NSEG + seg) * DS;
#pragma unroll
    for (int n = 0; n < DS; n += 4) {
        float4 pv = make_float4(__expf(a[n] * Sdt),     __expf(a[n + 1] * Sdt),
                                __expf(a[n + 2] * Sdt), __expf(a[n + 3] * Sdt));
        *(float4*)&P[pb + n] = pv;
        *(float4*)&Q[pb + n] = make_float4(h[n], h[n + 1], h[n + 2], h[n + 3]);
    }
}

__global__ void scanB(const float* __restrict__ P,
                      const float* __restrict__ Q,
                      float* __restrict__ hin)
{
    int i = blockIdx.x * 256 + threadIdx.x;     // over BSZ*DI
    if (i >= BSZ * DI) return;
    float h[DS];
#pragma unroll
    for (int n = 0; n < DS; n++) h[n] = 0.f;
    const int base = i * NSEG * DS;
    for (int s = 0; s < NSEG; s++) {
        const int o = base + s * DS;
#pragma unroll
        for (int n = 0; n < DS; n += 4) {
            float4 p = *(const float4*)&P[o + n];
            float4 q = *(const float4*)&Q[o + n];
            *(float4*)&hin[o + n] = make_float4(h[n], h[n+1], h[n+2], h[n+3]);
            h[n]     = fmaf(p.x, h[n],     q.x);
            h[n + 1] = fmaf(p.y, h[n + 1], q.y);
            h[n + 2] = fmaf(p.z, h[n + 2], q.z);
            h[n + 3] = fmaf(p.w, h[n + 3], q.w);
        }
    }
}

__global__ void __launch_bounds__(256) scanC(
    const float* __restrict__ dtp,
    const float* __restrict__ xp,
    const float* __restrict__ xdbl,
    const float* __restrict__ A_log,
    const float* __restrict__ Dp,
    const float* __restrict__ xz,
    const float* __restrict__ hin,
    __half* __restrict__ y)
{
    __shared__ float sB[TSEG][DS];
    __shared__ float sC[TSEG][DS];

    const int d   = blockIdx.x * 256 + threadIdx.x;
    const int seg = blockIdx.y;
    const int b   = blockIdx.z;
    const int t0  = seg * TSEG;

    for (int e = threadIdx.x; e < TSEG * DS; e += 256) {
        int t = e >> 4, n = e & 15;
        const float* row = &xdbl[(b * LEN + t0 + t) * 96];
        sB[t][n] = row[64 + n];
        sC[t][n] = row[80 + n];
    }
    __syncthreads();

    float a[DS], h[DS];
#pragma unroll
    for (int n = 0; n < DS; n++)
        a[n] = -__expf(A_log[d * DS + n]);
    {
        const int hb = ((b * DI + d) * NSEG + seg) * DS;
#pragma unroll
        for (int n = 0; n < DS; n += 4)
            *(float4*)&h[n] = *(const float4*)&hin[hb + n];
    }
    const float Dv = Dp[d];

    const int gi = (b * LEN + t0) * DI + d;
    const int zi = (b * LEN + t0) * 2 * DI + DI + d;
    float dt_c = dtp[gi], x_c = xp[gi], z_c = xz[zi];

    for (int t = 0; t < TSEG; t++) {
        float dt_n = 0.f, x_n = 0.f, z_n = 0.f;
        if (t + 1 < TSEG) {
            dt_n = dtp[gi + (t + 1) * DI];
            x_n  = xp[gi + (t + 1) * DI];
            z_n  = xz[zi + (t + 1) * 2 * DI];
        }
        const float dtx = dt_c * x_c;
        float bb[DS], cc[DS];
        *(float4*)&bb[0]  = *(const float4*)&sB[t][0];
        *(float4*)&bb[4]  = *(const float4*)&sB[t][4];
        *(float4*)&bb[8]  = *(const float4*)&sB[t][8];
        *(float4*)&bb[12] = *(const float4*)&sB[t][12];
        *(float4*)&cc[0]  = *(const float4*)&sC[t][0];
        *(float4*)&cc[4]  = *(const float4*)&sC[t][4];
        *(float4*)&cc[8]  = *(const float4*)&sC[t][8];
        *(float4*)&cc[12] = *(const float4*)&sC[t][12];
        float yv = 0.f;
#pragma unroll
        for (int n = 0; n < DS; n++) {
            float dA = __expf(dt_c * a[n]);
            h[n] = fmaf(dA, h[n], bb[n] * dtx);
            yv = fmaf(h[n], cc[n], yv);
        }
        float v  = yv + x_c * Dv;
        float gz = z_c / (1.f + __expf(-z_c));
        y[gi + t * DI] = __float2half_rn(v * gz);
        dt_c = dt_n; x_c = x_n; z_c = z_n;
    }
}

// ---------------------------------------------------------------------------
extern "C" void kernel_launch(void* const* d_in, const int* in_sizes, int n_in,
                              void* d_out, int out_size)
{
    const float* hidden = (const float*)d_in[0];
    const float* in_w   = (const float*)d_in[1];
    const float* conv_w = (const float*)d_in[2];
    const float* conv_b = (const float*)d_in[3];
    const float* xproj  = (const float*)d_in[4];
    const float* dtw    = (const float*)d_in[5];
    const float* dtb    = (const float*)d_in[6];
    const float* alog   = (const float*)d_in[7];
    const float* Dp     = (const float*)d_in[8];
    const float* outw   = (const float*)d_in[9];
    float* out = (float*)d_out;

    static float  *pxz = nullptr, *px = nullptr, *pxd = nullptr, *pdt = nullptr,
                  *pP = nullptr, *pQ = nullptr, *phin = nullptr;
    static __half *pxh = nullptr, *pdtrh = nullptr, *pyh = nullptr,
                  *phid = nullptr, *pinw = nullptr, *pxpw = nullptr,
                  *pdtw = nullptr, *potw = nullptr;
    if (!pxz) {
        cudaGetSymbolAddress((void**)&pxz,   g_xz);
        cudaGetSymbolAddress((void**)&px,    g_x);
        cudaGetSymbolAddress((void**)&pxd,   g_xdbl);
        cudaGetSymbolAddress((void**)&pdt,   g_dt);
        cudaGetSymbolAddress((void**)&pP,    g_P);
        cudaGetSymbolAddress((void**)&pQ,    g_Q);
        cudaGetSymbolAddress((void**)&phin,  g_hin);
        cudaGetSymbolAddress((void**)&pxh,   g_xh);
        cudaGetSymbolAddress((void**)&pdtrh, g_dtrh);
        cudaGetSymbolAddress((void**)&pyh,   g_yh);
        cudaGetSymbolAddress((void**)&phid,  g_hidh);
        cudaGetSymbolAddress((void**)&pinw,  g_inwh);
        cudaGetSymbolAddress((void**)&pxpw,  g_xpwh);
        cudaGetSymbolAddress((void**)&pdtw,  g_dtwh);
        cudaGetSymbolAddress((void**)&potw,  g_otwh);
        cudaFuncSetAttribute(gemm_h,
            cudaFuncAttributeMaxDynamicSharedMemorySize, SMEM_BYTES);
        cudaFuncSetAttribute(gemm_h,
            cudaFuncAttributePreferredSharedMemoryCarveout, 100);
    }

    // #1 weights -> fp16
    convert_w<<<(CWT + 511) / 512, 512>>>(in_w, xproj, dtw, outw);
    // #2 hidden -> fp16
    convert_hid<<<(CS0 / 4 + 511) / 512, 512>>>(hidden);
    // #3 zero split-K accumulator (x_dbl only)
    zero_kernel<<<(MROWS * 96 + 511) / 512, 512>>>(pxd, MROWS * 96);

    // #4 xz = hidden @ in_proj_w^T          (2048 x 4096 x 1024)  [profiled]
    gemm_h<<<dim3(2 * DI / 128, MROWS / 128, 1), 256, SMEM_BYTES>>>(
        phid, DM, pinw, DM, pxz, 2 * DI, 2 * DI, DM, nullptr, 0, 0);

    // #5 x = silu(conv1d(x) + b)
    conv_silu_kernel<<<(MROWS * DI) / 256, 256>>>(pxz, conv_w, conv_b, px, pxh);

    // #6 x_dbl = x @ x_proj_w^T             (2048 x 96 x 2048), split-K=8
    gemm_h<<<dim3(1, MROWS / 128, 8), 256, SMEM_BYTES>>>(
        pxh, DI, pxpw, DI, pxd, 96, 96, DI / 8, nullptr, 0, 1);

    // #7 dt_r slice -> half
    dtr2h_kernel<<<(MROWS * DR + 511) / 512, 512>>>(pxd, pdtrh);

    // #8 dt = softplus(dt_r @ dt_proj_w^T + b)   (2048 x 2048 x 64)
    gemm_h<<<dim3(DI / 128, MROWS / 128, 1), 256, SMEM_BYTES>>>(
        pdtrh, DR, pdtw, DR, pdt, DI, DI, DR, dtb, 1, 0);

    // #9-#11 segmented selective scan (state-per-thread)
    scanA<<<dim3(DI / 256, NSEG, BSZ), 256>>>(pdt, px, pxd, alog, pP, pQ);
    scanB<<<(BSZ * DI + 255) / 256, 256>>>(pP, pQ, phin);
    scanC<<<dim3(DI / 256, NSEG, BSZ), 256>>>(pdt, px, pxd, alog, Dp, pxz,
                                              phin, pyh);

    // #12 out = y @ out_proj_w^T            (2048 x 1024 x 2048)
    gemm_h<<<dim3(DM / 128, MROWS / 128, 1), 256, SMEM_BYTES>>>(
        pyh, DI, potw, DI, out, DM, DM, DI, nullptr, 0, 0);
}

// round 14
// speedup vs baseline: 1.0793x; 1.0793x over previous
#include <cuda_runtime.h>
#include <cuda_fp16.h>
#include <cstdint>

// Problem dims (fixed by the reference)
#define BSZ   2
#define LEN   1024
#define DM    1024
#define DI    2048
#define DS    16
#define DR    64
#define MROWS (BSZ*LEN)     // 2048
#define NSEG  16
#define TSEG  (LEN/NSEG)    // 64

// ---------------------------------------------------------------------------
// Scratch (allocation-free: __device__ globals)
// ---------------------------------------------------------------------------
__device__ float  g_xz   [MROWS * 2 * DI];  // in_proj out (x | z), fp32
__device__ float  g_x    [MROWS * DI];      // conv+silu out fp32 (scan)
__device__ __half g_xh   [MROWS * DI];      // conv+silu out half (x_proj A)
__device__ float  g_xdbl [MROWS * 96];      // x_proj out (dt_r | B | C) fp32
__device__ __half g_dtrh [MROWS * DR];      // x_dbl[:, :64] half (dt_proj A)
__device__ float  g_dt   [MROWS * DI];      // softplus dt fp32
__device__ __half g_yh   [MROWS * DI];      // gated scan out half (out_proj A)
__device__ float  g_part [MROWS * DM];      // out_proj split-K partial
__device__ float  g_P    [BSZ * DI * NSEG * DS];
__device__ float  g_Q    [BSZ * DI * NSEG * DS];
__device__ float  g_hin  [BSZ * DI * NSEG * DS];

__device__ __half g_hidh [MROWS * DM];      // hidden in half
__device__ __half g_inwh [2 * DI * DM];     // in_proj_w half
__device__ __half g_xpwh [96 * DI];         // x_proj_w half
__device__ __half g_dtwh [DI * DR];         // dt_proj_w half
__device__ __half g_otwh [DM * DI];         // out_proj_w half

__device__ __forceinline__ void cpa16(void* dst, const void* src, int sz) {
    uint32_t d = (uint32_t)__cvta_generic_to_shared(dst);
    asm volatile("cp.async.cg.shared.global [%0], [%1], 16, %2;\n"
                 :: "r"(d), "l"(src), "r"(sz) : "memory");
}

__device__ __forceinline__ void ldmx4(uint32_t& r0, uint32_t& r1,
                                      uint32_t& r2, uint32_t& r3,
                                      const void* p) {
    uint32_t a = (uint32_t)__cvta_generic_to_shared(p);
    asm volatile("ldmatrix.sync.aligned.m8n8.x4.shared.b16 {%0,%1,%2,%3}, [%4];"
                 : "=r"(r0), "=r"(r1), "=r"(r2), "=r"(r3) : "r"(a));
}

// ---------------------------------------------------------------------------
// fp16 GEMM v9 (round-12 best): C[M,N] (+)= A[M,Kslice] * W[N,Kslice]^T.
// CTA tile 128x128, 128 threads = 4 warps (2m x 2n), warp tile 64x64.
// Per K16 per warp: 8 ldmatrix.x4 + 32 HMMA.  NS=3 cp.async pipeline.
// grid.z splits K; Cz1: if non-null, blockIdx.z==1 writes there instead
// (atomic-free split-K=2).  atomic=1 -> atomicAdd; act==1 -> softplus(+bias).
// ---------------------------------------------------------------------------
#define BK 32
#define NS 3
#define SSTR 40
#define ABUF (128 * SSTR)
#define SMEM_BYTES (2 * NS * ABUF * 2)

__global__ void __launch_bounds__(128) gemm_h(
    const __half* __restrict__ A, int lda,
    const __half* __restrict__ W, int ldw,
    float* __restrict__ C, int ldc,
    int N, int ksplit,
    const float* __restrict__ bias, int act, int atomic,
    float* __restrict__ Cz1)
{
    extern __shared__ __half sm[];
    __half* Asm = sm;
    __half* Wsm = sm + NS * ABUF;

    if (Cz1 && blockIdx.z == 1) C = Cz1;

    const int bm   = blockIdx.y * 128;
    const int bn   = blockIdx.x * 128;
    const int kb   = blockIdx.z * ksplit;
    const int tid  = threadIdx.x;
    const int warp = tid >> 5;
    const int lane = tid & 31;
    const int wm   = (warp & 1) * 64;
    const int wn   = (warp >> 1) * 64;
    const int g    = lane >> 2;
    const int tg   = lane & 3;

    // loaders: 128 threads x 4 chunks of 16B cover 128 rows x 32 halfs
    const int lr = tid >> 2;               // rows lr, lr+32, lr+64, lr+96
    const int lc = (tid & 3) * 8;          // half offset 0,8,16,24
    const __half* ap = &A[(bm + lr) * lda + kb + lc];
    const __half* wp = &W[(bn + lr) * ldw + kb + lc];
    __half* asd = &Asm[lr * SSTR + lc];
    __half* wsd = &Wsm[lr * SSTR + lc];
    int wok[4];
#pragma unroll
    for (int q = 0; q < 4; q++) wok[q] = (bn + lr + 32 * q < N) ? 16 : 0;

    const int arow = wm + (lane & 15);
    const int akof = (lane >> 4) * 8;
    const int brow = wn + (lane & 7) + ((lane >> 4) << 3);
    const int bkof = ((lane >> 3) & 1) * 8;

    float acc[4][8][4];
#pragma unroll
    for (int i = 0; i < 4; i++)
#pragma unroll
        for (int j = 0; j < 8; j++)
#pragma unroll
            for (int c = 0; c < 4; c++) acc[i][j][c] = 0.f;

    const int nstage = ksplit / BK;

#pragma unroll
    for (int s = 0; s < NS - 1; s++) {
        const int ks = s * BK;
        const int vz = (s < nstage) ? 16 : 0;
#pragma unroll
        for (int q = 0; q < 4; q++) {
            cpa16(asd + (size_t)s * ABUF + 32 * q * SSTR,
                  ap + (size_t)32 * q * lda + ks, vz);
            cpa16(wsd + (size_t)s * ABUF + 32 * q * SSTR,
                  wp + (size_t)32 * q * ldw + ks, vz ? wok[q] : 0);
        }
        asm volatile("cp.async.commit_group;" ::: "memory");
    }

    for (int s = 0; s < nstage; s++) {
        const int buf = s % NS;
        asm volatile("cp.async.wait_group %0;" :: "n"(NS - 2) : "memory");
        __syncthreads();

        {
            const int sp = s + NS - 1;
            const int pb = sp % NS;
            const int ks = sp * BK;
            const int vz = (sp < nstage) ? 16 : 0;
#pragma unroll
            for (int q = 0; q < 4; q++) {
                cpa16(asd + (size_t)pb * ABUF + 32 * q * SSTR,
                      ap + (size_t)32 * q * lda + ks, vz);
                cpa16(wsd + (size_t)pb * ABUF + 32 * q * SSTR,
                      wp + (size_t)32 * q * ldw + ks, vz ? wok[q] : 0);
            }
            asm volatile("cp.async.commit_group;" ::: "memory");
        }

        const __half* ab = Asm + (size_t)buf * ABUF;
        const __half* wb = Wsm + (size_t)buf * ABUF;
#pragma unroll
        for (int kk = 0; kk < BK; kk += 16) {
            uint32_t a[4][4], b[16];
#pragma unroll
            for (int mi = 0; mi < 4; mi++)
                ldmx4(a[mi][0], a[mi][1], a[mi][2], a[mi][3],
                      ab + (arow + 16 * mi) * SSTR + kk + akof);
#pragma unroll
            for (int ni = 0; ni < 4; ni++)
                ldmx4(b[4 * ni], b[4 * ni + 1], b[4 * ni + 2], b[4 * ni + 3],
                      wb + (brow + 16 * ni) * SSTR + kk + bkof);
#pragma unroll
            for (int mi = 0; mi < 4; mi++)
#pragma unroll
                for (int jf = 0; jf < 8; jf++)
                    asm volatile(
                        "mma.sync.aligned.m16n8k16.row.col.f32.f16.f16.f32 "
                        "{%0,%1,%2,%3},{%4,%5,%6,%7},{%8,%9},{%0,%1,%2,%3};"
                        : "+f"(acc[mi][jf][0]), "+f"(acc[mi][jf][1]),
                          "+f"(acc[mi][jf][2]), "+f"(acc[mi][jf][3])
                        : "r"(a[mi][0]), "r"(a[mi][1]),
                          "r"(a[mi][2]), "r"(a[mi][3]),
                          "r"(b[2 * jf]), "r"(b[2 * jf + 1]));
        }
    }

#pragma unroll
    for (int mi = 0; mi < 4; mi++)
#pragma unroll
        for (int jf = 0; jf < 8; jf++) {
            const int nn = bn + wn + jf * 8 + tg * 2;
            if (nn < N) {
                const int m0 = bm + wm + mi * 16 + g;
                float v0 = acc[mi][jf][0], v1 = acc[mi][jf][1];
                float v2 = acc[mi][jf][2], v3 = acc[mi][jf][3];
                if (act) {
                    const float b0 = bias[nn], b1 = bias[nn + 1];
                    v0 += b0; v1 += b1; v2 += b0; v3 += b1;
                    v0 = (v0 > 20.f) ? v0 : log1pf(__expf(v0));
                    v1 = (v1 > 20.f) ? v1 : log1pf(__expf(v1));
                    v2 = (v2 > 20.f) ? v2 : log1pf(__expf(v2));
                    v3 = (v3 > 20.f) ? v3 : log1pf(__expf(v3));
                }
                if (atomic) {
                    atomicAdd(&C[m0 * ldc + nn],           v0);
                    atomicAdd(&C[m0 * ldc + nn + 1],       v1);
                    atomicAdd(&C[(m0 + 8) * ldc + nn],     v2);
                    atomicAdd(&C[(m0 + 8) * ldc + nn + 1], v3);
                } else {
                    *(float2*)&C[m0 * ldc + nn]       = make_float2(v0, v1);
                    *(float2*)&C[(m0 + 8) * ldc + nn] = make_float2(v2, v3);
                }
            }
        }
}

// ---------------------------------------------------------------------------
// fp32 -> fp16 conversion of hidden + all weights in one kernel.
// ---------------------------------------------------------------------------
#define CS0 (MROWS * DM)
#define CS1 (2 * DI * DM)
#define CS2 (96 * DI)
#define CS3 (DI * DR)
#define CS4 (DM * DI)
#define CTOT ((CS0 + CS1 + CS2 + CS3 + CS4) / 4)

__global__ void convert_all(const float* __restrict__ hid,
                            const float* __restrict__ inw,
                            const float* __restrict__ xpw,
                            const float* __restrict__ dtw,
                            const float* __restrict__ otw)
{
    int t = blockIdx.x * 512 + threadIdx.x;
    if (t >= CTOT) return;
    int i = t * 4;
    const float* src; __half* dst; int off;
    if (i < CS0) {
        src = hid; dst = g_hidh; off = i;
    } else if ((i -= CS0) < CS1) {
        src = inw; dst = g_inwh; off = i;
    } else if ((i -= CS1) < CS2) {
        src = xpw; dst = g_xpwh; off = i;
    } else if ((i -= CS2) < CS3) {
        src = dtw; dst = g_dtwh; off = i;
    } else {
        src = otw; dst = g_otwh; off = i - CS3;
    }
    float4 v = *(const float4*)(src + off);
    *(__half2*)(dst + off)     = __floats2half2_rn(v.x, v.y);
    *(__half2*)(dst + off + 2) = __floats2half2_rn(v.z, v.w);
}

__global__ void dtr2h_kernel(const float* __restrict__ xdbl, __half* __restrict__ d)
{
    int i = blockIdx.x * 512 + threadIdx.x;
    if (i < MROWS * DR) {
        int r = i >> 6, c = i & 63;
        d[i] = __float2half_rn(xdbl[r * 96 + c]);
    }
}

__global__ void zero_kernel(float* __restrict__ p, int n)
{
    int i = blockIdx.x * 512 + threadIdx.x;
    if (i < n) p[i] = 0.f;
}

// out += part  (split-K reduction for out_proj)
__global__ void add_kernel(float* __restrict__ out, const float* __restrict__ part)
{
    int i = blockIdx.x * 512 + threadIdx.x;
    if (i < MROWS * DM / 4) {
        float4 a = *(const float4*)(out + i * 4);
        float4 b = *(const float4*)(part + i * 4);
        a.x += b.x; a.y += b.y; a.z += b.z; a.w += b.w;
        *(float4*)(out + i * 4) = a;
    }
}

// ---------------------------------------------------------------------------
// Depthwise causal conv (K=4) + bias + SiLU.
// ---------------------------------------------------------------------------
__global__ void conv_silu_kernel(const float* __restrict__ xz,
                                 const float* __restrict__ w,
                                 const float* __restrict__ bias,
                                 float* __restrict__ xout,
                                 __half* __restrict__ xhout)
{
    int idx = blockIdx.x * blockDim.x + threadIdx.x;
    int d  = idx & (DI - 1);
    int bl = idx >> 11;
    int l  = bl & (LEN - 1);
    float accv = bias[d];
#pragma unroll
    for (int k = 0; k < 4; k++) {
        int ll = l + k - 3;
        if (ll >= 0)
            accv += xz[(bl + (ll - l)) * (2 * DI) + d] * w[d * 4 + k];
    }
    float v = accv / (1.f + __expf(-accv));
    xout[idx]  = v;
    xhout[idx] = __float2half_rn(v);
}

// ---------------------------------------------------------------------------
// Segmented selective scan, state-per-thread (16 states in registers).
// ---------------------------------------------------------------------------
__global__ void __launch_bounds__(256) scanA(
    const float* __restrict__ dtp,
    const float* __restrict__ xp,
    const float* __restrict__ xdbl,
    const float* __restrict__ A_log,
    float* __restrict__ P, float* __restrict__ Q)
{
    __shared__ float sB[TSEG][DS];

    const int d   = blockIdx.x * 256 + threadIdx.x;
    const int seg = blockIdx.y;
    const int b   = blockIdx.z;
    const int t0  = seg * TSEG;

    for (int e = threadIdx.x; e < TSEG * DS; e += 256) {
        int t = e >> 4, n = e & 15;
        sB[t][n] = xdbl[(b * LEN + t0 + t) * 96 + 64 + n];
    }
    __syncthreads();

    float a[DS], h[DS];
#pragma unroll
    for (int n = 0; n < DS; n++) {
        a[n] = -__expf(A_log[d * DS + n]);
        h[n] = 0.f;
    }

    const int gi = (b * LEN + t0) * DI + d;
    float Sdt = 0.f;
    float dt_c = dtp[gi], x_c = xp[gi];

    for (int t = 0; t < TSEG; t++) {
        float dt_n = 0.f, x_n = 0.f;
        if (t + 1 < TSEG) {
            dt_n = dtp[gi + (t + 1) * DI];
            x_n  = xp[gi + (t + 1) * DI];
        }
        const float dtx = dt_c * x_c;
        Sdt += dt_c;
        float bb[DS];
        *(float4*)&bb[0]  = *(const float4*)&sB[t][0];
        *(float4*)&bb[4]  = *(const float4*)&sB[t][4];
        *(float4*)&bb[8]  = *(const float4*)&sB[t][8];
        *(float4*)&bb[12] = *(const float4*)&sB[t][12];
#pragma unroll
        for (int n = 0; n < DS; n++) {
            float dA = __expf(dt_c * a[n]);
            h[n] = fmaf(dA, h[n], bb[n] * dtx);
        }
        dt_c = dt_n; x_c = x_n;
    }

    const int pb = ((b * DI + d) * NSEG + seg) * DS;
#pragma unroll
    for (int n = 0; n < DS; n += 4) {
        float4 pv = make_float4(__expf(a[n] * Sdt),     __expf(a[n + 1] * Sdt),
                                __expf(a[n + 2] * Sdt), __expf(a[n + 3] * Sdt));
        *(float4*)&P[pb + n] = pv;
        *(float4*)&Q[pb + n] = make_float4(h[n], h[n + 1], h[n + 2], h[n + 3]);
    }
}

__global__ void scanB(const float* __restrict__ P,
                      const float* __restrict__ Q,
                      float* __restrict__ hin)
{
    int i = blockIdx.x * 256 + threadIdx.x;     // over BSZ*DI
    if (i >= BSZ * DI) return;
    float h[DS];
#pragma unroll
    for (int n = 0; n < DS; n++) h[n] = 0.f;
    const int base = i * NSEG * DS;
    for (int s = 0; s < NSEG; s++) {
        const int o = base + s * DS;
#pragma unroll
        for (int n = 0; n < DS; n += 4) {
            float4 p = *(const float4*)&P[o + n];
            float4 q = *(const float4*)&Q[o + n];
            *(float4*)&hin[o + n] = make_float4(h[n], h[n+1], h[n+2], h[n+3]);
            h[n]     = fmaf(p.x, h[n],     q.x);
            h[n + 1] = fmaf(p.y, h[n + 1], q.y);
            h[n + 2] = fmaf(p.z, h[n + 2], q.z);
            h[n + 3] = fmaf(p.w, h[n + 3], q.w);
        }
    }
}

__global__ void __launch_bounds__(256) scanC(
    const float* __restrict__ dtp,
    const float* __restrict__ xp,
    const float* __restrict__ xdbl,
    const float* __restrict__ A_log,
    const float* __restrict__ Dp,
    const float* __restrict__ xz,
    const float* __restrict__ hin,
    __half* __restrict__ y)
{
    __shared__ float sB[TSEG][DS];
    __shared__ float sC[TSEG][DS];

    const int d   = blockIdx.x * 256 + threadIdx.x;
    const int seg = blockIdx.y;
    const int b   = blockIdx.z;
    const int t0  = seg * TSEG;

    for (int e = threadIdx.x; e < TSEG * DS; e += 256) {
        int t = e >> 4, n = e & 15;
        const float* row = &xdbl[(b * LEN + t0 + t) * 96];
        sB[t][n] = row[64 + n];
        sC[t][n] = row[80 + n];
    }
    __syncthreads();

    float a[DS], h[DS];
#pragma unroll
    for (int n = 0; n < DS; n++)
        a[n] = -__expf(A_log[d * DS + n]);
    {
        const int hb = ((b * DI + d) * NSEG + seg) * DS;
#pragma unroll
        for (int n = 0; n < DS; n += 4)
            *(float4*)&h[n] = *(const float4*)&hin[hb + n];
    }
    const float Dv = Dp[d];

    const int gi = (b * LEN + t0) * DI + d;
    const int zi = (b * LEN + t0) * 2 * DI + DI + d;
    float dt_c = dtp[gi], x_c = xp[gi], z_c = xz[zi];

    for (int t = 0; t < TSEG; t++) {
        float dt_n = 0.f, x_n = 0.f, z_n = 0.f;
        if (t + 1 < TSEG) {
            dt_n = dtp[gi + (t + 1) * DI];
            x_n  = xp[gi + (t + 1) * DI];
            z_n  = xz[zi + (t + 1) * 2 * DI];
        }
        const float dtx = dt_c * x_c;
        float bb[DS], cc[DS];
        *(float4*)&bb[0]  = *(const float4*)&sB[t][0];
        *(float4*)&bb[4]  = *(const float4*)&sB[t][4];
        *(float4*)&bb[8]  = *(const float4*)&sB[t][8];
        *(float4*)&bb[12] = *(const float4*)&sB[t][12];
        *(float4*)&cc[0]  = *(const float4*)&sC[t][0];
        *(float4*)&cc[4]  = *(const float4*)&sC[t][4];
        *(float4*)&cc[8]  = *(const float4*)&sC[t][8];
        *(float4*)&cc[12] = *(const float4*)&sC[t][12];
        float yv = 0.f;
#pragma unroll
        for (int n = 0; n < DS; n++) {
            float dA = __expf(dt_c * a[n]);
            h[n] = fmaf(dA, h[n], bb[n] * dtx);
            yv = fmaf(h[n], cc[n], yv);
        }
        float v  = yv + x_c * Dv;
        float gz = z_c / (1.f + __expf(-z_c));
        y[gi + t * DI] = __float2half_rn(v * gz);
        dt_c = dt_n; x_c = x_n; z_c = z_n;
    }
}

// ---------------------------------------------------------------------------
extern "C" void kernel_launch(void* const* d_in, const int* in_sizes, int n_in,
                              void* d_out, int out_size)
{
    const float* hidden = (const float*)d_in[0];
    const float* in_w   = (const float*)d_in[1];
    const float* conv_w = (const float*)d_in[2];
    const float* conv_b = (const float*)d_in[3];
    const float* xproj  = (const float*)d_in[4];
    const float* dtw    = (const float*)d_in[5];
    const float* dtb    = (const float*)d_in[6];
    const float* alog   = (const float*)d_in[7];
    const float* Dp     = (const float*)d_in[8];
    const float* outw   = (const float*)d_in[9];
    float* out = (float*)d_out;

    static float  *pxz = nullptr, *px = nullptr, *pxd = nullptr, *pdt = nullptr,
                  *pP = nullptr, *pQ = nullptr, *phin = nullptr, *ppart = nullptr;
    static __half *pxh = nullptr, *pdtrh = nullptr, *pyh = nullptr,
                  *phid = nullptr, *pinw = nullptr, *pxpw = nullptr,
                  *pdtw = nullptr, *potw = nullptr;
    if (!pxz) {
        cudaGetSymbolAddress((void**)&pxz,   g_xz);
        cudaGetSymbolAddress((void**)&px,    g_x);
        cudaGetSymbolAddress((void**)&pxd,   g_xdbl);
        cudaGetSymbolAddress((void**)&pdt,   g_dt);
        cudaGetSymbolAddress((void**)&pP,    g_P);
        cudaGetSymbolAddress((void**)&pQ,    g_Q);
        cudaGetSymbolAddress((void**)&phin,  g_hin);
        cudaGetSymbolAddress((void**)&ppart, g_part);
        cudaGetSymbolAddress((void**)&pxh,   g_xh);
        cudaGetSymbolAddress((void**)&pdtrh, g_dtrh);
        cudaGetSymbolAddress((void**)&pyh,   g_yh);
        cudaGetSymbolAddress((void**)&phid,  g_hidh);
        cudaGetSymbolAddress((void**)&pinw,  g_inwh);
        cudaGetSymbolAddress((void**)&pxpw,  g_xpwh);
        cudaGetSymbolAddress((void**)&pdtw,  g_dtwh);
        cudaGetSymbolAddress((void**)&potw,  g_otwh);
        cudaFuncSetAttribute(gemm_h,
            cudaFuncAttributeMaxDynamicSharedMemorySize, SMEM_BYTES);
        cudaFuncSetAttribute(gemm_h,
            cudaFuncAttributePreferredSharedMemoryCarveout, 100);
    }

    // #1 hidden + weights -> fp16 (one kernel)
    convert_all<<<(CTOT + 511) / 512, 512>>>(hidden, in_w, xproj, dtw, outw);
    // #2 zero split-K accumulator (x_dbl)
    zero_kernel<<<(MROWS * 96 + 511) / 512, 512>>>(pxd, MROWS * 96);

    // #3 xz = hidden @ in_proj_w^T          (2048 x 4096 x 1024)
    gemm_h<<<dim3(2 * DI / 128, MROWS / 128, 1), 128, SMEM_BYTES>>>(
        phid, DM, pinw, DM, pxz, 2 * DI, 2 * DI, DM, nullptr, 0, 0, nullptr);

    // #4 x = silu(conv1d(x) + b)
    conv_silu_kernel<<<(MROWS * DI) / 256, 256>>>(pxz, conv_w, conv_b, px, pxh);

    // #5 x_dbl = x @ x_proj_w^T             (2048 x 96 x 2048), split-K=8
    gemm_h<<<dim3(1, MROWS / 128, 8), 128, SMEM_BYTES>>>(
        pxh, DI, pxpw, DI, pxd, 96, 96, DI / 8, nullptr, 0, 1, nullptr);

    // #6 dt_r slice -> half
    dtr2h_kernel<<<(MROWS * DR + 511) / 512, 512>>>(pxd, pdtrh);

    // #7 dt = softplus(dt_r @ dt_proj_w^T + b)   (2048 x 2048 x 64)
    gemm_h<<<dim3(DI / 128, MROWS / 128, 1), 128, SMEM_BYTES>>>(
        pdtrh, DR, pdtw, DR, pdt, DI, DI, DR, dtb, 1, 0, nullptr);

    // #8-#10 segmented selective scan (state-per-thread)
    scanA<<<dim3(DI / 256, NSEG, BSZ), 256>>>(pdt, px, pxd, alog, pP, pQ);
    scanB<<<(BSZ * DI + 255) / 256, 256>>>(pP, pQ, phin);
    scanC<<<dim3(DI / 256, NSEG, BSZ), 256>>>(pdt, px, pxd, alog, Dp, pxz,
                                              phin, pyh);

    // #11 out = y @ out_proj_w^T   (2048 x 1024 x 2048), split-K=2 (no atomics)
    gemm_h<<<dim3(DM / 128, MROWS / 128, 2), 128, SMEM_BYTES>>>(
        pyh, DI, potw, DI, out, DM, DM, DI / 2, nullptr, 0, 0, ppart);

    // #12 out += partial
    add_kernel<<<(MROWS * DM / 4 + 511) / 512, 512>>>(out, ppart);
}

// round 15
// speedup vs baseline: 1.1390x; 1.0553x over previous
#include <cuda_runtime.h>
#include <cuda_fp16.h>
#include <cstdint>

// Problem dims (fixed by the reference)
#define BSZ   2
#define LEN   1024
#define DM    1024
#define DI    2048
#define DS    16
#define DR    64
#define MROWS (BSZ*LEN)     // 2048
#define NSEG  16
#define TSEG  (LEN/NSEG)    // 64

// ---------------------------------------------------------------------------
// Scratch (allocation-free: __device__ globals)
// ---------------------------------------------------------------------------
__device__ float  g_xz   [MROWS * 2 * DI];  // in_proj out (x | z), fp32
__device__ float  g_x    [MROWS * DI];      // conv+silu out fp32 (scan)
__device__ __half g_xh   [MROWS * DI];      // conv+silu out half (x_proj A)
__device__ float  g_xdbl [MROWS * 96];      // x_proj out (dt_r | B | C) fp32
__device__ __half g_dtrh [MROWS * DR];      // x_dbl[:, :64] half (dt_proj A)
__device__ float  g_dt   [MROWS * DI];      // softplus dt fp32
__device__ __half g_yh   [MROWS * DI];      // gated scan out half (out_proj A)
__device__ float  g_part [MROWS * DM];      // out_proj split-K partial
__device__ float  g_P    [BSZ * DI * NSEG * DS];
__device__ float  g_Q    [BSZ * DI * NSEG * DS];
__device__ float  g_hin  [BSZ * DI * NSEG * DS];

__device__ __half g_hidh [MROWS * DM];      // hidden in half
__device__ __half g_inwh [2 * DI * DM];     // in_proj_w half
__device__ __half g_xpwh [96 * DI];         // x_proj_w half
__device__ __half g_dtwh [DI * DR];         // dt_proj_w half
__device__ __half g_otwh [DM * DI];         // out_proj_w half

__device__ __forceinline__ void cpa16(void* dst, const void* src, int sz) {
    uint32_t d = (uint32_t)__cvta_generic_to_shared(dst);
    asm volatile("cp.async.cg.shared.global [%0], [%1], 16, %2;\n"
                 :: "r"(d), "l"(src), "r"(sz) : "memory");
}

__device__ __forceinline__ void ldmx4(uint32_t& r0, uint32_t& r1,
                                      uint32_t& r2, uint32_t& r3,
                                      const void* p) {
    uint32_t a = (uint32_t)__cvta_generic_to_shared(p);
    asm volatile("ldmatrix.sync.aligned.m8n8.x4.shared.b16 {%0,%1,%2,%3}, [%4];"
                 : "=r"(r0), "=r"(r1), "=r"(r2), "=r"(r3) : "r"(a));
}

// ---------------------------------------------------------------------------
// fp16 GEMM v11: C[M,N] (+)= A[M,Kslice] * W[N,Kslice]^T, fp32 acc.
// CTA tile 128x128, 128 threads = 4 warps (2m x 2n), warp tile 64x64.
// Per K16 per warp: 8 ldmatrix.x4 + 32 HMMA.  NS=4 cp.async pipeline
// (wait_group 2: two stages in flight during compute).
// grid.z splits K; Cz1: if non-null, blockIdx.z==1 writes there instead.
// atomic=1 -> atomicAdd; act==1 -> softplus(+bias).
// ---------------------------------------------------------------------------
#define BK 32
#define NS 4
#define SSTR 40
#define ABUF (128 * SSTR)
#define SMEM_BYTES (2 * NS * ABUF * 2)     // 81920

__global__ void __launch_bounds__(128) gemm_h(
    const __half* __restrict__ A, int lda,
    const __half* __restrict__ W, int ldw,
    float* __restrict__ C, int ldc,
    int N, int ksplit,
    const float* __restrict__ bias, int act, int atomic,
    float* __restrict__ Cz1)
{
    extern __shared__ __half sm[];
    __half* Asm = sm;
    __half* Wsm = sm + NS * ABUF;

    if (Cz1 && blockIdx.z == 1) C = Cz1;

    const int bm   = blockIdx.y * 128;
    const int bn   = blockIdx.x * 128;
    const int kb   = blockIdx.z * ksplit;
    const int tid  = threadIdx.x;
    const int warp = tid >> 5;
    const int lane = tid & 31;
    const int wm   = (warp & 1) * 64;
    const int wn   = (warp >> 1) * 64;
    const int g    = lane >> 2;
    const int tg   = lane & 3;

    // loaders: 128 threads x 4 chunks of 16B cover 128 rows x 32 halfs
    const int lr = tid >> 2;               // rows lr, lr+32, lr+64, lr+96
    const int lc = (tid & 3) * 8;          // half offset 0,8,16,24
    const __half* ap = &A[(bm + lr) * lda + kb + lc];
    const __half* wp = &W[(bn + lr) * ldw + kb + lc];
    __half* asd = &Asm[lr * SSTR + lc];
    __half* wsd = &Wsm[lr * SSTR + lc];
    int wok[4];
#pragma unroll
    for (int q = 0; q < 4; q++) wok[q] = (bn + lr + 32 * q < N) ? 16 : 0;

    const int arow = wm + (lane & 15);
    const int akof = (lane >> 4) * 8;
    const int brow = wn + (lane & 7) + ((lane >> 4) << 3);
    const int bkof = ((lane >> 3) & 1) * 8;

    float acc[4][8][4];
#pragma unroll
    for (int i = 0; i < 4; i++)
#pragma unroll
        for (int j = 0; j < 8; j++)
#pragma unroll
            for (int c = 0; c < 4; c++) acc[i][j][c] = 0.f;

    const int nstage = ksplit / BK;

#pragma unroll
    for (int s = 0; s < NS - 1; s++) {
        const int ks = s * BK;
        const int vz = (s < nstage) ? 16 : 0;
#pragma unroll
        for (int q = 0; q < 4; q++) {
            cpa16(asd + (size_t)s * ABUF + 32 * q * SSTR,
                  ap + (size_t)32 * q * lda + ks, vz);
            cpa16(wsd + (size_t)s * ABUF + 32 * q * SSTR,
                  wp + (size_t)32 * q * ldw + ks, vz ? wok[q] : 0);
        }
        asm volatile("cp.async.commit_group;" ::: "memory");
    }

    for (int s = 0; s < nstage; s++) {
        const int buf = s % NS;
        asm volatile("cp.async.wait_group %0;" :: "n"(NS - 2) : "memory");
        __syncthreads();

        {
            const int sp = s + NS - 1;
            const int pb = sp % NS;
            const int ks = sp * BK;
            const int vz = (sp < nstage) ? 16 : 0;
#pragma unroll
            for (int q = 0; q < 4; q++) {
                cpa16(asd + (size_t)pb * ABUF + 32 * q * SSTR,
                      ap + (size_t)32 * q * lda + ks, vz);
                cpa16(wsd + (size_t)pb * ABUF + 32 * q * SSTR,
                      wp + (size_t)32 * q * ldw + ks, vz ? wok[q] : 0);
            }
            asm volatile("cp.async.commit_group;" ::: "memory");
        }

        const __half* ab = Asm + (size_t)buf * ABUF;
        const __half* wb = Wsm + (size_t)buf * ABUF;
#pragma unroll
        for (int kk = 0; kk < BK; kk += 16) {
            uint32_t a[4][4], b[16];
#pragma unroll
            for (int mi = 0; mi < 4; mi++)
                ldmx4(a[mi][0], a[mi][1], a[mi][2], a[mi][3],
                      ab + (arow + 16 * mi) * SSTR + kk + akof);
#pragma unroll
            for (int ni = 0; ni < 4; ni++)
                ldmx4(b[4 * ni], b[4 * ni + 1], b[4 * ni + 2], b[4 * ni + 3],
                      wb + (brow + 16 * ni) * SSTR + kk + bkof);
#pragma unroll
            for (int mi = 0; mi < 4; mi++)
#pragma unroll
                for (int jf = 0; jf < 8; jf++)
                    asm volatile(
                        "mma.sync.aligned.m16n8k16.row.col.f32.f16.f16.f32 "
                        "{%0,%1,%2,%3},{%4,%5,%6,%7},{%8,%9},{%0,%1,%2,%3};"
                        : "+f"(acc[mi][jf][0]), "+f"(acc[mi][jf][1]),
                          "+f"(acc[mi][jf][2]), "+f"(acc[mi][jf][3])
                        : "r"(a[mi][0]), "r"(a[mi][1]),
                          "r"(a[mi][2]), "r"(a[mi][3]),
                          "r"(b[2 * jf]), "r"(b[2 * jf + 1]));
        }
    }

#pragma unroll
    for (int mi = 0; mi < 4; mi++)
#pragma unroll
        for (int jf = 0; jf < 8; jf++) {
            const int nn = bn + wn + jf * 8 + tg * 2;
            if (nn < N) {
                const int m0 = bm + wm + mi * 16 + g;
                float v0 = acc[mi][jf][0], v1 = acc[mi][jf][1];
                float v2 = acc[mi][jf][2], v3 = acc[mi][jf][3];
                if (act) {
                    const float b0 = bias[nn], b1 = bias[nn + 1];
                    v0 += b0; v1 += b1; v2 += b0; v3 += b1;
                    v0 = (v0 > 20.f) ? v0 : log1pf(__expf(v0));
                    v1 = (v1 > 20.f) ? v1 : log1pf(__expf(v1));
                    v2 = (v2 > 20.f) ? v2 : log1pf(__expf(v2));
                    v3 = (v3 > 20.f) ? v3 : log1pf(__expf(v3));
                }
                if (atomic) {
                    atomicAdd(&C[m0 * ldc + nn],           v0);
                    atomicAdd(&C[m0 * ldc + nn + 1],       v1);
                    atomicAdd(&C[(m0 + 8) * ldc + nn],     v2);
                    atomicAdd(&C[(m0 + 8) * ldc + nn + 1], v3);
                } else {
                    *(float2*)&C[m0 * ldc + nn]       = make_float2(v0, v1);
                    *(float2*)&C[(m0 + 8) * ldc + nn] = make_float2(v2, v3);
                }
            }
        }
}

// ---------------------------------------------------------------------------
// fp32 -> fp16 conversion of hidden + all weights, plus zeroing of the
// x_proj split-K accumulator, in ONE kernel.
// ---------------------------------------------------------------------------
#define CS0 (MROWS * DM)
#define CS1 (2 * DI * DM)
#define CS2 (96 * DI)
#define CS3 (DI * DR)
#define CS4 (DM * DI)
#define CCVT ((CS0 + CS1 + CS2 + CS3 + CS4) / 4)
#define CZRO (MROWS * 96 / 4)
#define CTOT (CCVT + CZRO)

__global__ void convert_all(const float* __restrict__ hid,
                            const float* __restrict__ inw,
                            const float* __restrict__ xpw,
                            const float* __restrict__ dtw,
                            const float* __restrict__ otw,
                            float* __restrict__ xdbl_zero)
{
    int t = blockIdx.x * 512 + threadIdx.x;
    if (t >= CTOT) return;
    if (t >= CCVT) {
        *(float4*)(xdbl_zero + (t - CCVT) * 4) = make_float4(0.f, 0.f, 0.f, 0.f);
        return;
    }
    int i = t * 4;
    const float* src; __half* dst; int off;
    if (i < CS0) {
        src = hid; dst = g_hidh; off = i;
    } else if ((i -= CS0) < CS1) {
        src = inw; dst = g_inwh; off = i;
    } else if ((i -= CS1) < CS2) {
        src = xpw; dst = g_xpwh; off = i;
    } else if ((i -= CS2) < CS3) {
        src = dtw; dst = g_dtwh; off = i;
    } else {
        src = otw; dst = g_otwh; off = i - CS3;
    }
    float4 v = *(const float4*)(src + off);
    *(__half2*)(dst + off)     = __floats2half2_rn(v.x, v.y);
    *(__half2*)(dst + off + 2) = __floats2half2_rn(v.z, v.w);
}

__global__ void dtr2h_kernel(const float* __restrict__ xdbl, __half* __restrict__ d)
{
    int i = blockIdx.x * 512 + threadIdx.x;
    if (i < MROWS * DR) {
        int r = i >> 6, c = i & 63;
        d[i] = __float2half_rn(xdbl[r * 96 + c]);
    }
}

// out += part  (split-K reduction for out_proj)
__global__ void add_kernel(float* __restrict__ out, const float* __restrict__ part)
{
    int i = blockIdx.x * 512 + threadIdx.x;
    if (i < MROWS * DM / 4) {
        float4 a = *(const float4*)(out + i * 4);
        float4 b = *(const float4*)(part + i * 4);
        a.x += b.x; a.y += b.y; a.z += b.z; a.w += b.w;
        *(float4*)(out + i * 4) = a;
    }
}

// ---------------------------------------------------------------------------
// Depthwise causal conv (K=4) + bias + SiLU, v2: 4 outputs (along l) per
// thread; 7 input loads per 4 outputs (1.75x read amplification vs 4x).
// ---------------------------------------------------------------------------
__global__ void conv_silu_kernel(const float* __restrict__ xz,
                                 const float* __restrict__ w,
                                 const float* __restrict__ bias,
                                 float* __restrict__ xout,
                                 __half* __restrict__ xhout)
{
    int i = blockIdx.x * 256 + threadIdx.x;   // over MROWS*DI/4
    int d   = i & (DI - 1);
    int lq  = i >> 11;
    int bl0 = lq * 4;
    int l0  = bl0 & (LEN - 1);

    const float4 wv = *(const float4*)&w[d * 4];
    const float bv = bias[d];
    const float* base = xz + (size_t)bl0 * (2 * DI) + d;

    float x[7];
#pragma unroll
    for (int j = 0; j < 3; j++)
        x[j] = (l0 + j >= 3) ? base[(j - 3) * (2 * DI)] : 0.f;
#pragma unroll
    for (int j = 3; j < 7; j++)
        x[j] = base[(j - 3) * (2 * DI)];

#pragma unroll
    for (int j = 0; j < 4; j++) {
        float acc = bv;
        acc = fmaf(wv.x, x[j],     acc);
        acc = fmaf(wv.y, x[j + 1], acc);
        acc = fmaf(wv.z, x[j + 2], acc);
        acc = fmaf(wv.w, x[j + 3], acc);
        float v = acc / (1.f + __expf(-acc));
        int idx = (bl0 + j) * DI + d;
        xout[idx]  = v;
        xhout[idx] = __float2half_rn(v);
    }
}

// ---------------------------------------------------------------------------
// Segmented selective scan, state-per-thread (16 states in registers).
// ---------------------------------------------------------------------------
__global__ void __launch_bounds__(256) scanA(
    const float* __restrict__ dtp,
    const float* __restrict__ xp,
    const float* __restrict__ xdbl,
    const float* __restrict__ A_log,
    float* __restrict__ P, float* __restrict__ Q)
{
    __shared__ float sB[TSEG][DS];

    const int d   = blockIdx.x * 256 + threadIdx.x;
    const int seg = blockIdx.y;
    const int b   = blockIdx.z;
    const int t0  = seg * TSEG;

    for (int e = threadIdx.x; e < TSEG * DS; e += 256) {
        int t = e >> 4, n = e & 15;
        sB[t][n] = xdbl[(b * LEN + t0 + t) * 96 + 64 + n];
    }
    __syncthreads();

    float a[DS], h[DS];
#pragma unroll
    for (int n = 0; n < DS; n++) {
        a[n] = -__expf(A_log[d * DS + n]);
        h[n] = 0.f;
    }

    const int gi = (b * LEN + t0) * DI + d;
    float Sdt = 0.f;
    float dt_c = dtp[gi], x_c = xp[gi];

    for (int t = 0; t < TSEG; t++) {
        float dt_n = 0.f, x_n = 0.f;
        if (t + 1 < TSEG) {
            dt_n = dtp[gi + (t + 1) * DI];
            x_n  = xp[gi + (t + 1) * DI];
        }
        const float dtx = dt_c * x_c;
        Sdt += dt_c;
        float bb[DS];
        *(float4*)&bb[0]  = *(const float4*)&sB[t][0];
        *(float4*)&bb[4]  = *(const float4*)&sB[t][4];
        *(float4*)&bb[8]  = *(const float4*)&sB[t][8];
        *(float4*)&bb[12] = *(const float4*)&sB[t][12];
#pragma unroll
        for (int n = 0; n < DS; n++) {
            float dA = __expf(dt_c * a[n]);
            h[n] = fmaf(dA, h[n], bb[n] * dtx);
        }
        dt_c = dt_n; x_c = x_n;
    }

    const int pb = ((b * DI + d) * NSEG + seg) * DS;
#pragma unroll
    for (int n = 0; n < DS; n += 4) {
        float4 pv = make_float4(__expf(a[n] * Sdt),     __expf(a[n + 1] * Sdt),
                                __expf(a[n + 2] * Sdt), __expf(a[n + 3] * Sdt));
        *(float4*)&P[pb + n] = pv;
        *(float4*)&Q[pb + n] = make_float4(h[n], h[n + 1], h[n + 2], h[n + 3]);
    }
}

__global__ void scanB(const float* __restrict__ P,
                      const float* __restrict__ Q,
                      float* __restrict__ hin)
{
    int i = blockIdx.x * 256 + threadIdx.x;     // over BSZ*DI
    if (i >= BSZ * DI) return;
    float h[DS];
#pragma unroll
    for (int n = 0; n < DS; n++) h[n] = 0.f;
    const int base = i * NSEG * DS;
    for (int s = 0; s < NSEG; s++) {
        const int o = base + s * DS;
#pragma unroll
        for (int n = 0; n < DS; n += 4) {
            float4 p = *(const float4*)&P[o + n];
            float4 q = *(const float4*)&Q[o + n];
            *(float4*)&hin[o + n] = make_float4(h[n], h[n+1], h[n+2], h[n+3]);
            h[n]     = fmaf(p.x, h[n],     q.x);
            h[n + 1] = fmaf(p.y, h[n + 1], q.y);
            h[n + 2] = fmaf(p.z, h[n + 2], q.z);
            h[n + 3] = fmaf(p.w, h[n + 3], q.w);
        }
    }
}

__global__ void __launch_bounds__(256) scanC(
    const float* __restrict__ dtp,
    const float* __restrict__ xp,
    const float* __restrict__ xdbl,
    const float* __restrict__ A_log,
    const float* __restrict__ Dp,
    const float* __restrict__ xz,
    const float* __restrict__ hin,
    __half* __restrict__ y)
{
    __shared__ float sB[TSEG][DS];
    __shared__ float sC[TSEG][DS];

    const int d   = blockIdx.x * 256 + threadIdx.x;
    const int seg = blockIdx.y;
    const int b   = blockIdx.z;
    const int t0  = seg * TSEG;

    for (int e = threadIdx.x; e < TSEG * DS; e += 256) {
        int t = e >> 4, n = e & 15;
        const float* row = &xdbl[(b * LEN + t0 + t) * 96];
        sB[t][n] = row[64 + n];
        sC[t][n] = row[80 + n];
    }
    __syncthreads();

    float a[DS], h[DS];
#pragma unroll
    for (int n = 0; n < DS; n++)
        a[n] = -__expf(A_log[d * DS + n]);
    {
        const int hb = ((b * DI + d) * NSEG + seg) * DS;
#pragma unroll
        for (int n = 0; n < DS; n += 4)
            *(float4*)&h[n] = *(const float4*)&hin[hb + n];
    }
    const float Dv = Dp[d];

    const int gi = (b * LEN + t0) * DI + d;
    const int zi = (b * LEN + t0) * 2 * DI + DI + d;
    float dt_c = dtp[gi], x_c = xp[gi], z_c = xz[zi];

    for (int t = 0; t < TSEG; t++) {
        float dt_n = 0.f, x_n = 0.f, z_n = 0.f;
        if (t + 1 < TSEG) {
            dt_n = dtp[gi + (t + 1) * DI];
            x_n  = xp[gi + (t + 1) * DI];
            z_n  = xz[zi + (t + 1) * 2 * DI];
        }
        const float dtx = dt_c * x_c;
        float bb[DS], cc[DS];
        *(float4*)&bb[0]  = *(const float4*)&sB[t][0];
        *(float4*)&bb[4]  = *(const float4*)&sB[t][4];
        *(float4*)&bb[8]  = *(const float4*)&sB[t][8];
        *(float4*)&bb[12] = *(const float4*)&sB[t][12];
        *(float4*)&cc[0]  = *(const float4*)&sC[t][0];
        *(float4*)&cc[4]  = *(const float4*)&sC[t][4];
        *(float4*)&cc[8]  = *(const float4*)&sC[t][8];
        *(float4*)&cc[12] = *(const float4*)&sC[t][12];
        float yv = 0.f;
#pragma unroll
        for (int n = 0; n < DS; n++) {
            float dA = __expf(dt_c * a[n]);
            h[n] = fmaf(dA, h[n], bb[n] * dtx);
            yv = fmaf(h[n], cc[n], yv);
        }
        float v  = yv + x_c * Dv;
        float gz = z_c / (1.f + __expf(-z_c));
        y[gi + t * DI] = __float2half_rn(v * gz);
        dt_c = dt_n; x_c = x_n; z_c = z_n;
    }
}

// ---------------------------------------------------------------------------
extern "C" void kernel_launch(void* const* d_in, const int* in_sizes, int n_in,
                              void* d_out, int out_size)
{
    const float* hidden = (const float*)d_in[0];
    const float* in_w   = (const float*)d_in[1];
    const float* conv_w = (const float*)d_in[2];
    const float* conv_b = (const float*)d_in[3];
    const float* xproj  = (const float*)d_in[4];
    const float* dtw    = (const float*)d_in[5];
    const float* dtb    = (const float*)d_in[6];
    const float* alog   = (const float*)d_in[7];
    const float* Dp     = (const float*)d_in[8];
    const float* outw   = (const float*)d_in[9];
    float* out = (float*)d_out;

    static float  *pxz = nullptr, *px = nullptr, *pxd = nullptr, *pdt = nullptr,
                  *pP = nullptr, *pQ = nullptr, *phin = nullptr, *ppart = nullptr;
    static __half *pxh = nullptr, *pdtrh = nullptr, *pyh = nullptr,
                  *phid = nullptr, *pinw = nullptr, *pxpw = nullptr,
                  *pdtw = nullptr, *potw = nullptr;
    if (!pxz) {
        cudaGetSymbolAddress((void**)&pxz,   g_xz);
        cudaGetSymbolAddress((void**)&px,    g_x);
        cudaGetSymbolAddress((void**)&pxd,   g_xdbl);
        cudaGetSymbolAddress((void**)&pdt,   g_dt);
        cudaGetSymbolAddress((void**)&pP,    g_P);
        cudaGetSymbolAddress((void**)&pQ,    g_Q);
        cudaGetSymbolAddress((void**)&phin,  g_hin);
        cudaGetSymbolAddress((void**)&ppart, g_part);
        cudaGetSymbolAddress((void**)&pxh,   g_xh);
        cudaGetSymbolAddress((void**)&pdtrh, g_dtrh);
        cudaGetSymbolAddress((void**)&pyh,   g_yh);
        cudaGetSymbolAddress((void**)&phid,  g_hidh);
        cudaGetSymbolAddress((void**)&pinw,  g_inwh);
        cudaGetSymbolAddress((void**)&pxpw,  g_xpwh);
        cudaGetSymbolAddress((void**)&pdtw,  g_dtwh);
        cudaGetSymbolAddress((void**)&potw,  g_otwh);
        cudaFuncSetAttribute(gemm_h,
            cudaFuncAttributeMaxDynamicSharedMemorySize, SMEM_BYTES);
        cudaFuncSetAttribute(gemm_h,
            cudaFuncAttributePreferredSharedMemoryCarveout, 100);
    }

    // #1 hidden + weights -> fp16, and zero x_dbl accumulator (one kernel)
    convert_all<<<(CTOT + 511) / 512, 512>>>(hidden, in_w, xproj, dtw, outw, pxd);

    // #2 xz = hidden @ in_proj_w^T          (2048 x 4096 x 1024)
    gemm_h<<<dim3(2 * DI / 128, MROWS / 128, 1), 128, SMEM_BYTES>>>(
        phid, DM, pinw, DM, pxz, 2 * DI, 2 * DI, DM, nullptr, 0, 0, nullptr);

    // #3 x = silu(conv1d(x) + b)
    conv_silu_kernel<<<(MROWS * DI / 4) / 256, 256>>>(pxz, conv_w, conv_b, px, pxh);

    // #4 x_dbl = x @ x_proj_w^T             (2048 x 96 x 2048), split-K=8
    gemm_h<<<dim3(1, MROWS / 128, 8), 128, SMEM_BYTES>>>(
        pxh, DI, pxpw, DI, pxd, 96, 96, DI / 8, nullptr, 0, 1, nullptr);

    // #5 dt_r slice -> half
    dtr2h_kernel<<<(MROWS * DR + 511) / 512, 512>>>(pxd, pdtrh);

    // #6 dt = softplus(dt_r @ dt_proj_w^T + b)   (2048 x 2048 x 64)
    gemm_h<<<dim3(DI / 128, MROWS / 128, 1), 128, SMEM_BYTES>>>(
        pdtrh, DR, pdtw, DR, pdt, DI, DI, DR, dtb, 1, 0, nullptr);

    // #7-#9 segmented selective scan (state-per-thread)
    scanA<<<dim3(DI / 256, NSEG, BSZ), 256>>>(pdt, px, pxd, alog, pP, pQ);
    scanB<<<(BSZ * DI + 255) / 256, 256>>>(pP, pQ, phin);
    scanC<<<dim3(DI / 256, NSEG, BSZ), 256>>>(pdt, px, pxd, alog, Dp, pxz,
                                              phin, pyh);

    // #10 out = y @ out_proj_w^T   (2048 x 1024 x 2048), split-K=2 (no atomics)
    gemm_h<<<dim3(DM / 128, MROWS / 128, 2), 128, SMEM_BYTES>>>(
        pyh, DI, potw, DI, out, DM, DM, DI / 2, nullptr, 0, 0, ppart);

    // #11 out += partial
    add_kernel<<<(MROWS * DM / 4 + 511) / 512, 512>>>(out, ppart);
}